// round 13
// baseline (speedup 1.0000x reference)
#include <cuda_runtime.h>
#include <cuda_bf16.h>
#include <cuda_fp16.h>
#include <mma.h>
#include <math.h>
#include <cstdint>

using namespace nvcuda;

#define NTOK 8192
#define DIM  1024
#define HID  4096
#define NEXP 8
#define NPAIR (NTOK*2)
#define ROWPAD 128
#define LN_EPS 1e-5f

// ---------------- scratch (device globals) ----------------
__device__ float g_topkw[NPAIR];
__device__ int   g_topki[NPAIR];
__device__ int   g_cnt[NEXP];
__device__ int   g_off[NEXP + 1];
__device__ int   g_pairs[NPAIR];
__device__ int   g_pairof[NPAIR];

__device__ __half g_x16[(size_t)(NPAIR + ROWPAD) * DIM];
__device__ __half g_h16[(size_t)(NPAIR + ROWPAD) * HID];
__device__ __half g_w1_16[(size_t)NEXP * HID * DIM];
__device__ __half g_w2_16[(size_t)NEXP * DIM * HID];
__device__ float  g_y[(size_t)NPAIR * DIM];

// ---------------- helpers ----------------
__device__ __forceinline__ void cvt4_store(__half* dst, float4 f) {
    __half2 a = __floats2half2_rn(f.x, f.y);
    __half2 b = __floats2half2_rn(f.z, f.w);
    *reinterpret_cast<__half2*>(dst)     = a;
    *reinterpret_cast<__half2*>(dst + 2) = b;
}

__device__ __forceinline__ void cpa16(void* sdst, const void* gsrc) {
    uint32_t s = (uint32_t)__cvta_generic_to_shared(sdst);
    asm volatile("cp.async.cg.shared.global [%0], [%1], 16;\n" :: "r"(s), "l"(gsrc));
}
__device__ __forceinline__ void cp_commit() { asm volatile("cp.async.commit_group;\n"); }
template <int N> __device__ __forceinline__ void cp_wait() {
    asm volatile("cp.async.wait_group %0;\n" :: "n"(N));
}

// ---------------- kernel 1: gating + (fused) W2 -> fp16 ----------------
__global__ void gate_kernel(const float* __restrict__ x,
                            const float* __restrict__ gw,
                            const float* __restrict__ gb,
                            const float* __restrict__ w2) {
    int t = blockIdx.x;
    int tid = threadIdx.x;                 // 256 threads
    int wid = tid >> 5, lane = tid & 31;

    float acc[NEXP];
#pragma unroll
    for (int e = 0; e < NEXP; e++) acc[e] = 0.f;

    const float* xr = x + (size_t)t * DIM;
    for (int i = tid; i < DIM; i += 256) {
        float xv = xr[i];
#pragma unroll
        for (int e = 0; e < NEXP; e++) acc[e] += xv * gw[e * DIM + i];
    }
#pragma unroll
    for (int e = 0; e < NEXP; e++)
#pragma unroll
        for (int o = 16; o > 0; o >>= 1) acc[e] += __shfl_down_sync(0xffffffffu, acc[e], o);

    __shared__ float part[8][NEXP];
    if (lane == 0) {
#pragma unroll
        for (int e = 0; e < NEXP; e++) part[wid][e] = acc[e];
    }
    __syncthreads();

    if (tid == 0) {
        float lg[NEXP], p[NEXP];
#pragma unroll
        for (int e = 0; e < NEXP; e++) {
            float s = gb[e];
#pragma unroll
            for (int w = 0; w < 8; w++) s += part[w][e];
            lg[e] = s;
        }
        float m = lg[0];
#pragma unroll
        for (int e = 1; e < NEXP; e++) m = fmaxf(m, lg[e]);
        float se = 0.f;
#pragma unroll
        for (int e = 0; e < NEXP; e++) { p[e] = expf(lg[e] - m); se += p[e]; }
        float inv = 1.f / se;
#pragma unroll
        for (int e = 0; e < NEXP; e++) p[e] *= inv;

        int i0 = 0;
#pragma unroll
        for (int e = 1; e < NEXP; e++) if (p[e] > p[i0]) i0 = e;
        int i1 = (i0 == 0) ? 1 : 0;
#pragma unroll
        for (int e = 0; e < NEXP; e++) if (e != i0 && p[e] > p[i1]) i1 = e;

        float b = expf(p[i1] - p[i0]);
        float w0 = 1.f / (1.f + b);
        float w1 = b / (1.f + b);

        g_topki[2 * t]     = i0;  g_topki[2 * t + 1] = i1;
        g_topkw[2 * t]     = w0;  g_topkw[2 * t + 1] = w1;
    }

    // fused: convert W2 (8388608 float4) across 8192*256 threads, 4 each
    size_t base = (size_t)blockIdx.x * 256 + tid;
#pragma unroll
    for (int rep = 0; rep < 4; rep++) {
        size_t i = base + (size_t)rep * 2097152;
        float4 f = reinterpret_cast<const float4*>(w2)[i];
        cvt4_store(&g_w2_16[i * 4], f);
    }
}

// ---------------- kernel 2: route = count + prefix + scatter (one block) ----------------
__global__ void route_kernel() {
    __shared__ int sc[NEXP];
    __shared__ int so[NEXP];
    int tid = threadIdx.x;                 // 1024 threads
    if (tid < NEXP) sc[tid] = 0;
    __syncthreads();
    for (int i = tid; i < NPAIR; i += 1024) atomicAdd(&sc[g_topki[i]], 1);
    __syncthreads();
    if (tid == 0) {
        int s = 0;
#pragma unroll
        for (int e = 0; e < NEXP; e++) {
            so[e] = s;
            g_off[e] = s;
            g_cnt[e] = sc[e];
            s += sc[e];
        }
        g_off[NEXP] = s;
    }
    __syncthreads();
    if (tid < NEXP) sc[tid] = so[tid];
    __syncthreads();
    for (int i = tid; i < NPAIR; i += 1024) {
        int e = g_topki[i];
        int pos = atomicAdd(&sc[e], 1);
        g_pairs[pos] = i;
        g_pairof[i] = pos;
    }
}

// ---------------- kernel 3: gather x (fp16) + (fused) W1 -> fp16 ----------------
__global__ void gather_kernel(const float* __restrict__ x, const float* __restrict__ w1) {
    int pr = blockIdx.x;
    int tid = threadIdx.x;                 // 256 threads
    int tok = g_pairs[pr] >> 1;
    float4 f = reinterpret_cast<const float4*>(x + (size_t)tok * DIM)[tid];
    cvt4_store(&g_x16[(size_t)pr * DIM + tid * 4], f);

    size_t base = (size_t)pr * 256 + tid;
#pragma unroll
    for (int rep = 0; rep < 2; rep++) {
        size_t i = base + (size_t)rep * 4194304;
        float4 w = reinterpret_cast<const float4*>(w1)[i];
        cvt4_store(&g_w1_16[i * 4], w);
    }
}

// ---------------- grouped GEMM: fp16, 128x256x64, 64x64 warp tiles, 3-stage ----------
// PASS1: g_h16 = relu(Xg @ W1^T + b1)   K=1024, Nn=4096
// PASS2: g_y   =      H  @ W2^T + b2    K=4096, Nn=1024
#define BM 128
#define BN 256
#define BK 64
#define STR 72                      // 144B rows: 16B-aligned, conflict-free LDSM phases
#define A_PL (BM * STR)             // 9216 elems
#define B_PL (BN * STR)             // 18432 elems
#define BUF_ELEMS (A_PL + B_PL)     // 27648 elems = 55296 B
#define STAGES 3
#define SMEM_BYTES (STAGES * BUF_ELEMS * 2)   // 165888 B (occ 1 CTA/SM)

template <bool PASS1>
__global__ __launch_bounds__(256, 1)
void moe_gemm(const float* __restrict__ Bias) {
    constexpr int K  = PASS1 ? DIM : HID;
    constexpr int Nn = PASS1 ? HID : DIM;
    constexpr int KT = K / BK;
    const __half* __restrict__ Ag = PASS1 ? g_x16 : g_h16;
    const __half* __restrict__ Wg = PASS1 ? g_w1_16 : g_w2_16;

    int e = blockIdx.z;
    int cnt = g_cnt[e];
    int m0 = blockIdx.x * BM;
    if (m0 >= cnt) return;
    int r0 = g_off[e] + m0;
    int n0 = blockIdx.y * BN;

    const __half* We = Wg + (size_t)e * Nn * K;
    const float* be = Bias + (size_t)e * Nn;

    extern __shared__ __align__(16) unsigned char smem_raw[];
    __half* smem = reinterpret_cast<__half*>(smem_raw);

    int tid = threadIdx.x;
    int wid = tid >> 5, lane = tid & 31;
    int wm = wid & 1;        // 2 warps along M: 64 rows each
    int wn = wid >> 1;       // 4 warps along N: 64 cols each

    // loader: 3072 x 16B chunks/stage, 12 per thread. Precompute per-thread bases:
    // slot t covers id = tid + t*256; id<1024 -> A(row=id>>3), else B(row=(id-1024)>>3)
    const __half* lsrc[12];
    uint32_t      ldst[12];
#pragma unroll
    for (int t = 0; t < 12; t++) {
        int id = tid + t * 256;
        if (id < 1024) {
            int row = id >> 3, ch = id & 7;
            lsrc[t] = Ag + (size_t)(r0 + row) * K + ch * 8;
            ldst[t] = row * STR + ch * 8;                 // within A plane
        } else {
            int id2 = id - 1024;
            int row = id2 >> 3, ch = id2 & 7;
            lsrc[t] = We + (size_t)(n0 + row) * K + ch * 8;
            ldst[t] = A_PL + row * STR + ch * 8;          // within B plane
        }
    }
    auto load_panel = [&](int kt, int b) {
        const int k0 = kt * BK;
        __half* bb = smem + b * BUF_ELEMS;
#pragma unroll
        for (int t = 0; t < 12; t++) cpa16(bb + ldst[t], lsrc[t] + k0);
    };

    wmma::fragment<wmma::accumulator, 16, 16, 16, float> acc[4][4];
#pragma unroll
    for (int i = 0; i < 4; i++)
#pragma unroll
        for (int j = 0; j < 4; j++) wmma::fill_fragment(acc[i][j], 0.f);

    load_panel(0, 0); cp_commit();
    load_panel(1, 1); cp_commit();

    for (int kt = 0; kt < KT; kt++) {
        if (kt + 1 < KT) cp_wait<1>(); else cp_wait<0>();   // load(kt) complete
        // Single barrier per kt: all warps finished compute(kt-1), the last reader of
        // stage (kt-1)%3 == (kt+2)%3, so the prefetch below cannot race.
        __syncthreads();
        if (kt + 2 < KT) { load_panel(kt + 2, (kt + 2) % STAGES); cp_commit(); }

        const __half* bA = smem + (kt % STAGES) * BUF_ELEMS;
        const __half* bB = bA + A_PL;

#pragma unroll
        for (int kk = 0; kk < 4; kk++) {
            wmma::fragment<wmma::matrix_a, 16, 16, 16, __half, wmma::row_major> a[4];
#pragma unroll
            for (int i = 0; i < 4; i++)
                wmma::load_matrix_sync(a[i], bA + (wm * 64 + i * 16) * STR + kk * 16, STR);
#pragma unroll
            for (int j = 0; j < 4; j++) {
                wmma::fragment<wmma::matrix_b, 16, 16, 16, __half, wmma::col_major> bf;
                wmma::load_matrix_sync(bf, bB + (wn * 64 + j * 16) * STR + kk * 16, STR);
#pragma unroll
                for (int i = 0; i < 4; i++)
                    wmma::mma_sync(acc[i][j], a[i], bf, acc[i][j]);
            }
        }
    }
    __syncthreads();   // protect smem before epilogue staging reuse

    // epilogue: per-warp 64x64 fp32 stage in smem (16KB/warp, 128KB total <= 162KB)
    float* stage = reinterpret_cast<float*>(smem_raw) + (size_t)wid * 4096;
#pragma unroll
    for (int i = 0; i < 4; i++)
#pragma unroll
        for (int j = 0; j < 4; j++)
            wmma::store_matrix_sync(stage + i * 16 * 64 + j * 16, acc[i][j], 64,
                                    wmma::mem_row_major);
    __syncwarp();

    int rem = cnt - m0;   // valid rows in this tile
    for (int it = lane; it < 1024; it += 32) {    // 64x64 elems as float4
        int row_loc = it >> 4;
        int c4 = (it & 15) * 4;
        int rtile = wm * 64 + row_loc;
        if (rtile < rem) {
            float4 v = *reinterpret_cast<float4*>(stage + row_loc * 64 + c4);
            int gcol = n0 + wn * 64 + c4;
            float4 bv = *reinterpret_cast<const float4*>(&be[gcol]);
            v.x += bv.x; v.y += bv.y; v.z += bv.z; v.w += bv.w;
            size_t grow = (size_t)(r0 + rtile);
            if (PASS1) {
                v.x = fmaxf(v.x, 0.f); v.y = fmaxf(v.y, 0.f);
                v.z = fmaxf(v.z, 0.f); v.w = fmaxf(v.w, 0.f);
                cvt4_store(&g_h16[grow * HID + gcol], v);
            } else {
                *reinterpret_cast<float4*>(&g_y[grow * DIM + gcol]) = v;
            }
        }
    }
}

// ---------------- kernel 6: combine + residual + LayerNorm ----------------
__global__ void finalize_kernel(const float* __restrict__ x,
                                const float* __restrict__ lnw,
                                const float* __restrict__ lnb,
                                float* __restrict__ out) {
    int t = blockIdx.x;
    int tid = threadIdx.x;
    int wid = tid >> 5, lane = tid & 31;

    float w0 = g_topkw[2 * t], w1 = g_topkw[2 * t + 1];
    size_t p0 = (size_t)g_pairof[2 * t] * DIM;
    size_t p1 = (size_t)g_pairof[2 * t + 1] * DIM;

    __shared__ float r[DIM];
    __shared__ float ps[8][2];

    float s = 0.f, s2 = 0.f;
    for (int i = tid; i < DIM; i += 256) {
        float v = x[(size_t)t * DIM + i] + w0 * g_y[p0 + i] + w1 * g_y[p1 + i];
        r[i] = v;
        s += v;
        s2 += v * v;
    }
#pragma unroll
    for (int o = 16; o > 0; o >>= 1) {
        s  += __shfl_down_sync(0xffffffffu, s, o);
        s2 += __shfl_down_sync(0xffffffffu, s2, o);
    }
    if (lane == 0) { ps[wid][0] = s; ps[wid][1] = s2; }
    __syncthreads();
    if (tid == 0) {
        float a = 0.f, b = 0.f;
#pragma unroll
        for (int w = 0; w < 8; w++) { a += ps[w][0]; b += ps[w][1]; }
        float mu = a / (float)DIM;
        float var = b / (float)DIM - mu * mu;
        ps[0][0] = mu;
        ps[0][1] = rsqrtf(var + LN_EPS);
    }
    __syncthreads();
    float mu = ps[0][0], inv = ps[0][1];
    for (int i = tid; i < DIM; i += 256)
        out[(size_t)t * DIM + i] = (r[i] - mu) * inv * lnw[i] + lnb[i];
}

// ---------------- launch ----------------
extern "C" void kernel_launch(void* const* d_in, const int* in_sizes, int n_in,
                              void* d_out, int out_size) {
    (void)in_sizes; (void)n_in; (void)out_size;
    const float* x   = (const float*)d_in[0];
    const float* gw  = (const float*)d_in[1];
    const float* gb  = (const float*)d_in[2];
    const float* w1  = (const float*)d_in[3];
    const float* b1  = (const float*)d_in[4];
    const float* w2  = (const float*)d_in[5];
    const float* b2  = (const float*)d_in[6];
    const float* lnw = (const float*)d_in[7];
    const float* lnb = (const float*)d_in[8];
    float* out = (float*)d_out;

    cudaFuncSetAttribute(moe_gemm<true>,  cudaFuncAttributeMaxDynamicSharedMemorySize, SMEM_BYTES);
    cudaFuncSetAttribute(moe_gemm<false>, cudaFuncAttributeMaxDynamicSharedMemorySize, SMEM_BYTES);

    gate_kernel<<<NTOK, 256>>>(x, gw, gb, w2);                         // launch 0 (+W2 cvt)
    route_kernel<<<1, 1024>>>();                                       // launch 1
    gather_kernel<<<NPAIR, 256>>>(x, w1);                              // launch 2 (+W1 cvt)
    moe_gemm<true><<<dim3(NPAIR / BM, HID / BN, NEXP), 256, SMEM_BYTES>>>(b1);   // launch 3 <- ncu
    moe_gemm<false><<<dim3(NPAIR / BM, DIM / BN, NEXP), 256, SMEM_BYTES>>>(b2);  // launch 4
    finalize_kernel<<<NTOK, 256>>>(x, lnw, lnb, out);                  // launch 5
}

// round 14
// speedup vs baseline: 1.1155x; 1.1155x over previous
#include <cuda_runtime.h>
#include <cuda_bf16.h>
#include <cuda_fp16.h>
#include <mma.h>
#include <math.h>
#include <cstdint>

using namespace nvcuda;

#define NTOK 8192
#define DIM  1024
#define HID  4096
#define NEXP 8
#define NPAIR (NTOK*2)
#define ROWPAD 128
#define LN_EPS 1e-5f

// ---------------- scratch (device globals) ----------------
__device__ float g_topkw[NPAIR];
__device__ int   g_topki[NPAIR];
__device__ int   g_cnt[NEXP];
__device__ int   g_off[NEXP + 1];
__device__ int   g_pairs[NPAIR];
__device__ int   g_pairof[NPAIR];

__device__ __half g_x16[(size_t)(NPAIR + ROWPAD) * DIM];
__device__ __half g_h16[(size_t)(NPAIR + ROWPAD) * HID];
__device__ __half g_w1_16[(size_t)NEXP * HID * DIM];
__device__ __half g_w2_16[(size_t)NEXP * DIM * HID];
__device__ float  g_y[2][(size_t)NPAIR * DIM];      // split-K halves for GEMM2

// ---------------- helpers ----------------
__device__ __forceinline__ void cvt4_store(__half* dst, float4 f) {
    __half2 a = __floats2half2_rn(f.x, f.y);
    __half2 b = __floats2half2_rn(f.z, f.w);
    *reinterpret_cast<__half2*>(dst)     = a;
    *reinterpret_cast<__half2*>(dst + 2) = b;
}

__device__ __forceinline__ void cpa16(void* sdst, const void* gsrc) {
    uint32_t s = (uint32_t)__cvta_generic_to_shared(sdst);
    asm volatile("cp.async.cg.shared.global [%0], [%1], 16;\n" :: "r"(s), "l"(gsrc));
}
__device__ __forceinline__ void cp_commit() { asm volatile("cp.async.commit_group;\n"); }
template <int N> __device__ __forceinline__ void cp_wait() {
    asm volatile("cp.async.wait_group %0;\n" :: "n"(N));
}

// ---------------- kernel 1: gating + (fused) W2 -> fp16 ----------------
__global__ void gate_kernel(const float* __restrict__ x,
                            const float* __restrict__ gw,
                            const float* __restrict__ gb,
                            const float* __restrict__ w2) {
    int t = blockIdx.x;
    int tid = threadIdx.x;                 // 256 threads
    int wid = tid >> 5, lane = tid & 31;

    float acc[NEXP];
#pragma unroll
    for (int e = 0; e < NEXP; e++) acc[e] = 0.f;

    const float* xr = x + (size_t)t * DIM;
    for (int i = tid; i < DIM; i += 256) {
        float xv = xr[i];
#pragma unroll
        for (int e = 0; e < NEXP; e++) acc[e] += xv * gw[e * DIM + i];
    }
#pragma unroll
    for (int e = 0; e < NEXP; e++)
#pragma unroll
        for (int o = 16; o > 0; o >>= 1) acc[e] += __shfl_down_sync(0xffffffffu, acc[e], o);

    __shared__ float part[8][NEXP];
    if (lane == 0) {
#pragma unroll
        for (int e = 0; e < NEXP; e++) part[wid][e] = acc[e];
    }
    __syncthreads();

    if (tid == 0) {
        float lg[NEXP], p[NEXP];
#pragma unroll
        for (int e = 0; e < NEXP; e++) {
            float s = gb[e];
#pragma unroll
            for (int w = 0; w < 8; w++) s += part[w][e];
            lg[e] = s;
        }
        float m = lg[0];
#pragma unroll
        for (int e = 1; e < NEXP; e++) m = fmaxf(m, lg[e]);
        float se = 0.f;
#pragma unroll
        for (int e = 0; e < NEXP; e++) { p[e] = expf(lg[e] - m); se += p[e]; }
        float inv = 1.f / se;
#pragma unroll
        for (int e = 0; e < NEXP; e++) p[e] *= inv;

        int i0 = 0;
#pragma unroll
        for (int e = 1; e < NEXP; e++) if (p[e] > p[i0]) i0 = e;
        int i1 = (i0 == 0) ? 1 : 0;
#pragma unroll
        for (int e = 0; e < NEXP; e++) if (e != i0 && p[e] > p[i1]) i1 = e;

        float b = expf(p[i1] - p[i0]);
        float w0 = 1.f / (1.f + b);
        float w1 = b / (1.f + b);

        g_topki[2 * t]     = i0;  g_topki[2 * t + 1] = i1;
        g_topkw[2 * t]     = w0;  g_topkw[2 * t + 1] = w1;
    }

    // fused: convert W2 (8388608 float4) across 8192*256 threads, 4 each
    size_t base = (size_t)blockIdx.x * 256 + tid;
#pragma unroll
    for (int rep = 0; rep < 4; rep++) {
        size_t i = base + (size_t)rep * 2097152;
        float4 f = reinterpret_cast<const float4*>(w2)[i];
        cvt4_store(&g_w2_16[i * 4], f);
    }
}

// ---------------- kernel 2: route = count + prefix + scatter (one block) ----------------
__global__ void route_kernel() {
    __shared__ int sc[NEXP];
    __shared__ int so[NEXP];
    int tid = threadIdx.x;                 // 1024 threads
    if (tid < NEXP) sc[tid] = 0;
    __syncthreads();
    for (int i = tid; i < NPAIR; i += 1024) atomicAdd(&sc[g_topki[i]], 1);
    __syncthreads();
    if (tid == 0) {
        int s = 0;
#pragma unroll
        for (int e = 0; e < NEXP; e++) {
            so[e] = s;
            g_off[e] = s;
            g_cnt[e] = sc[e];
            s += sc[e];
        }
        g_off[NEXP] = s;
    }
    __syncthreads();
    if (tid < NEXP) sc[tid] = so[tid];
    __syncthreads();
    for (int i = tid; i < NPAIR; i += 1024) {
        int e = g_topki[i];
        int pos = atomicAdd(&sc[e], 1);
        g_pairs[pos] = i;
        g_pairof[i] = pos;
    }
}

// ---------------- kernel 3: gather x (fp16) + (fused) W1 -> fp16 ----------------
__global__ void gather_kernel(const float* __restrict__ x, const float* __restrict__ w1) {
    int pr = blockIdx.x;
    int tid = threadIdx.x;                 // 256 threads
    int tok = g_pairs[pr] >> 1;
    float4 f = reinterpret_cast<const float4*>(x + (size_t)tok * DIM)[tid];
    cvt4_store(&g_x16[(size_t)pr * DIM + tid * 4], f);

    size_t base = (size_t)pr * 256 + tid;
#pragma unroll
    for (int rep = 0; rep < 2; rep++) {
        size_t i = base + (size_t)rep * 4194304;
        float4 w = reinterpret_cast<const float4*>(w1)[i];
        cvt4_store(&g_w1_16[i * 4], w);
    }
}

// ---------------- grouped GEMM: fp16, 128x128x64, 2 CTAs/SM, 2-stage (R10 proven) ----
// PASS1: g_h16  = relu(Xg @ W1^T + b1)            K=1024, Nn=4096, SPLIT=1
// PASS2: g_y[s] = H @ W2[ks half]^T (+b2 if s==0) K=4096, Nn=1024, SPLIT=2
#define BM 128
#define BN 128
#define BK 64
#define STR 72                      // 144B rows: 16B-aligned, conflict-free LDSM phases
#define PL (BM * STR)               // per-plane elems = 9216
#define BUF_ELEMS (2 * PL)          // A|B = 18432 elems = 36864 B
#define SMEM_BYTES (2 * BUF_ELEMS * 2)   // 2 stages = 73728 B (-> 2 CTAs/SM)

template <bool PASS1>
__global__ __launch_bounds__(256, 2)
void moe_gemm(const float* __restrict__ Bias) {
    constexpr int K  = PASS1 ? DIM : HID;
    constexpr int Nn = PASS1 ? HID : DIM;
    constexpr int SPLIT = PASS1 ? 1 : 2;       // split-K for GEMM2 (wave-tail fix)
    constexpr int KT = K / BK / SPLIT;
    const __half* __restrict__ Ag = PASS1 ? g_x16 : g_h16;
    const __half* __restrict__ Wg = PASS1 ? g_w1_16 : g_w2_16;

    int e = blockIdx.z;
    int cnt = g_cnt[e];
    int m0 = blockIdx.x * BM;
    if (m0 >= cnt) return;
    int r0 = g_off[e] + m0;
    int sp = blockIdx.y % SPLIT;               // K-split index (0 for PASS1)
    int n0 = (blockIdx.y / SPLIT) * BN;
    int kbase = sp * (K / SPLIT);

    const __half* We = Wg + (size_t)e * Nn * K;
    const float* be = Bias + (size_t)e * Nn;

    extern __shared__ __align__(16) unsigned char smem_raw[];
    __half* smem = reinterpret_cast<__half*>(smem_raw);

    int tid = threadIdx.x;
    int wid = tid >> 5, lane = tid & 31;
    int wm = wid & 3;        // 4 warps along M: 32 rows each
    int wn = wid >> 2;       // 2 warps along N: 64 cols each

    // stage loader: 2048 x 16B chunks, 8 per thread. planes: 0=A 1=B
    auto load_panel = [&](int kt, int b) {
        const int k0 = kbase + kt * BK;
        __half* bb = smem + b * BUF_ELEMS;
#pragma unroll
        for (int t = 0; t < 8; t++) {
            int id = tid + t * 256;
            int plane = id >> 10, rem = id & 1023;
            int row = rem >> 3, ch = rem & 7;
            const __half* src = plane
                ? We + (size_t)(n0 + row) * K + k0 + ch * 8
                : Ag + (size_t)(r0 + row) * K + k0 + ch * 8;
            cpa16(bb + plane * PL + row * STR + ch * 8, src);
        }
    };

    wmma::fragment<wmma::accumulator, 16, 16, 16, float> acc[2][4];
#pragma unroll
    for (int i = 0; i < 2; i++)
#pragma unroll
        for (int j = 0; j < 4; j++) wmma::fill_fragment(acc[i][j], 0.f);

    load_panel(0, 0);
    cp_commit();

    for (int kt = 0; kt < KT; kt++) {
        if (kt + 1 < KT) {
            load_panel(kt + 1, (kt + 1) & 1);
            cp_commit();
            cp_wait<1>();
        } else {
            cp_wait<0>();
        }
        __syncthreads();

        const __half* bA = smem + (kt & 1) * BUF_ELEMS;
        const __half* bB = bA + PL;

#pragma unroll
        for (int kk = 0; kk < 4; kk++) {
            wmma::fragment<wmma::matrix_a, 16, 16, 16, __half, wmma::row_major> a[2];
#pragma unroll
            for (int i = 0; i < 2; i++)
                wmma::load_matrix_sync(a[i], bA + (wm * 32 + i * 16) * STR + kk * 16, STR);
#pragma unroll
            for (int j = 0; j < 4; j++) {
                wmma::fragment<wmma::matrix_b, 16, 16, 16, __half, wmma::col_major> bf;
                wmma::load_matrix_sync(bf, bB + (wn * 64 + j * 16) * STR + kk * 16, STR);
#pragma unroll
                for (int i = 0; i < 2; i++)
                    wmma::mma_sync(acc[i][j], a[i], bf, acc[i][j]);
            }
        }
        __syncthreads();
    }

    // epilogue: per-warp 32x64 fp32 stage in smem (8KB/warp)
    float* stage = reinterpret_cast<float*>(smem_raw) + (size_t)wid * 2048;
#pragma unroll
    for (int i = 0; i < 2; i++)
#pragma unroll
        for (int j = 0; j < 4; j++)
            wmma::store_matrix_sync(stage + i * 16 * 64 + j * 16, acc[i][j], 64,
                                    wmma::mem_row_major);
    __syncwarp();

    int rem = cnt - m0;   // valid rows in this tile
    bool add_bias = PASS1 || (sp == 0);       // bias added exactly once across splits
    for (int it = lane; it < 512; it += 32) {     // 32x64 elems as float4
        int row_loc = it >> 4;
        int c4 = (it & 15) * 4;
        int rtile = wm * 32 + row_loc;
        if (rtile < rem) {
            float4 v = *reinterpret_cast<float4*>(stage + row_loc * 64 + c4);
            int gcol = n0 + wn * 64 + c4;
            if (add_bias) {
                float4 bv = *reinterpret_cast<const float4*>(&be[gcol]);
                v.x += bv.x; v.y += bv.y; v.z += bv.z; v.w += bv.w;
            }
            size_t grow = (size_t)(r0 + rtile);
            if (PASS1) {
                v.x = fmaxf(v.x, 0.f); v.y = fmaxf(v.y, 0.f);
                v.z = fmaxf(v.z, 0.f); v.w = fmaxf(v.w, 0.f);
                cvt4_store(&g_h16[grow * HID + gcol], v);
            } else {
                *reinterpret_cast<float4*>(&g_y[sp][grow * DIM + gcol]) = v;
            }
        }
    }
}

// ---------------- kernel 6: combine (both K-splits) + residual + LayerNorm -----------
__global__ void finalize_kernel(const float* __restrict__ x,
                                const float* __restrict__ lnw,
                                const float* __restrict__ lnb,
                                float* __restrict__ out) {
    int t = blockIdx.x;
    int tid = threadIdx.x;
    int wid = tid >> 5, lane = tid & 31;

    float w0 = g_topkw[2 * t], w1 = g_topkw[2 * t + 1];
    size_t p0 = (size_t)g_pairof[2 * t] * DIM;
    size_t p1 = (size_t)g_pairof[2 * t + 1] * DIM;

    __shared__ float r[DIM];
    __shared__ float ps[8][2];

    float s = 0.f, s2 = 0.f;
    for (int i = tid; i < DIM; i += 256) {
        float y0 = g_y[0][p0 + i] + g_y[1][p0 + i];
        float y1 = g_y[0][p1 + i] + g_y[1][p1 + i];
        float v = x[(size_t)t * DIM + i] + w0 * y0 + w1 * y1;
        r[i] = v;
        s += v;
        s2 += v * v;
    }
#pragma unroll
    for (int o = 16; o > 0; o >>= 1) {
        s  += __shfl_down_sync(0xffffffffu, s, o);
        s2 += __shfl_down_sync(0xffffffffu, s2, o);
    }
    if (lane == 0) { ps[wid][0] = s; ps[wid][1] = s2; }
    __syncthreads();
    if (tid == 0) {
        float a = 0.f, b = 0.f;
#pragma unroll
        for (int w = 0; w < 8; w++) { a += ps[w][0]; b += ps[w][1]; }
        float mu = a / (float)DIM;
        float var = b / (float)DIM - mu * mu;
        ps[0][0] = mu;
        ps[0][1] = rsqrtf(var + LN_EPS);
    }
    __syncthreads();
    float mu = ps[0][0], inv = ps[0][1];
    for (int i = tid; i < DIM; i += 256)
        out[(size_t)t * DIM + i] = (r[i] - mu) * inv * lnw[i] + lnb[i];
}

// ---------------- launch ----------------
extern "C" void kernel_launch(void* const* d_in, const int* in_sizes, int n_in,
                              void* d_out, int out_size) {
    (void)in_sizes; (void)n_in; (void)out_size;
    const float* x   = (const float*)d_in[0];
    const float* gw  = (const float*)d_in[1];
    const float* gb  = (const float*)d_in[2];
    const float* w1  = (const float*)d_in[3];
    const float* b1  = (const float*)d_in[4];
    const float* w2  = (const float*)d_in[5];
    const float* b2  = (const float*)d_in[6];
    const float* lnw = (const float*)d_in[7];
    const float* lnb = (const float*)d_in[8];
    float* out = (float*)d_out;

    cudaFuncSetAttribute(moe_gemm<true>,  cudaFuncAttributeMaxDynamicSharedMemorySize, SMEM_BYTES);
    cudaFuncSetAttribute(moe_gemm<false>, cudaFuncAttributeMaxDynamicSharedMemorySize, SMEM_BYTES);

    gate_kernel<<<NTOK, 256>>>(x, gw, gb, w2);                         // launch 0 (+W2 cvt)
    route_kernel<<<1, 1024>>>();                                       // launch 1
    gather_kernel<<<NPAIR, 256>>>(x, w1);                              // launch 2 (+W1 cvt)
    moe_gemm<true><<<dim3(NPAIR / BM, HID / BN, NEXP), 256, SMEM_BYTES>>>(b1);        // 3 <- ncu
    moe_gemm<false><<<dim3(NPAIR / BM, (DIM / BN) * 2, NEXP), 256, SMEM_BYTES>>>(b2); // 4 split-K
    finalize_kernel<<<NTOK, 256>>>(x, lnw, lnb, out);                  // launch 5
}

// round 15
// speedup vs baseline: 1.1622x; 1.0419x over previous
#include <cuda_runtime.h>
#include <cuda_bf16.h>
#include <cuda_fp16.h>
#include <mma.h>
#include <math.h>
#include <cstdint>

using namespace nvcuda;

#define NTOK 8192
#define DIM  1024
#define HID  4096
#define NEXP 8
#define NPAIR (NTOK*2)
#define ROWPAD 128
#define LN_EPS 1e-5f

// ---------------- scratch (device globals) ----------------
__device__ float g_topkw[NPAIR];
__device__ int   g_topki[NPAIR];
__device__ int   g_cnt[NEXP];
__device__ int   g_off[NEXP + 1];
__device__ int   g_pairs[NPAIR];
__device__ int   g_pairof[NPAIR];

__device__ __half g_x16[(size_t)NTOK * DIM];                  // token order (no gather)
__device__ __half g_h16[(size_t)(NPAIR + ROWPAD) * HID];      // pair order
__device__ __half g_w1_16[(size_t)NEXP * HID * DIM];
__device__ __half g_w2_16[(size_t)NEXP * DIM * HID];
__device__ float  g_y[(size_t)NPAIR * DIM];

// ---------------- helpers ----------------
__device__ __forceinline__ void cvt4_store(__half* dst, float4 f) {
    __half2 a = __floats2half2_rn(f.x, f.y);
    __half2 b = __floats2half2_rn(f.z, f.w);
    *reinterpret_cast<__half2*>(dst)     = a;
    *reinterpret_cast<__half2*>(dst + 2) = b;
}

__device__ __forceinline__ void cpa16(void* sdst, const void* gsrc) {
    uint32_t s = (uint32_t)__cvta_generic_to_shared(sdst);
    asm volatile("cp.async.cg.shared.global [%0], [%1], 16;\n" :: "r"(s), "l"(gsrc));
}
__device__ __forceinline__ void cp_commit() { asm volatile("cp.async.commit_group;\n"); }
template <int N> __device__ __forceinline__ void cp_wait() {
    asm volatile("cp.async.wait_group %0;\n" :: "n"(N));
}

// ---------------- kernel 1: gating + x->fp16 + W1/W2 -> fp16 ----------------
__global__ void gate_kernel(const float* __restrict__ x,
                            const float* __restrict__ gw,
                            const float* __restrict__ gb,
                            const float* __restrict__ w1,
                            const float* __restrict__ w2) {
    int t = blockIdx.x;
    int tid = threadIdx.x;                 // 256 threads; 256*4 = 1024 = DIM exactly
    int wid = tid >> 5, lane = tid & 31;

    // one float4 of x per thread: feeds both the gating GEMV and the fp16 conversion
    float4 f = reinterpret_cast<const float4*>(x + (size_t)t * DIM)[tid];
    cvt4_store(&g_x16[(size_t)t * DIM + tid * 4], f);

    float acc[NEXP];
#pragma unroll
    for (int e = 0; e < NEXP; e++) {
        float4 g = reinterpret_cast<const float4*>(gw + (size_t)e * DIM)[tid];
        acc[e] = f.x * g.x + f.y * g.y + f.z * g.z + f.w * g.w;
    }
#pragma unroll
    for (int e = 0; e < NEXP; e++)
#pragma unroll
        for (int o = 16; o > 0; o >>= 1) acc[e] += __shfl_down_sync(0xffffffffu, acc[e], o);

    __shared__ float part[8][NEXP];
    if (lane == 0) {
#pragma unroll
        for (int e = 0; e < NEXP; e++) part[wid][e] = acc[e];
    }
    __syncthreads();

    if (tid == 0) {
        float lg[NEXP], p[NEXP];
#pragma unroll
        for (int e = 0; e < NEXP; e++) {
            float s = gb[e];
#pragma unroll
            for (int w = 0; w < 8; w++) s += part[w][e];
            lg[e] = s;
        }
        float m = lg[0];
#pragma unroll
        for (int e = 1; e < NEXP; e++) m = fmaxf(m, lg[e]);
        float se = 0.f;
#pragma unroll
        for (int e = 0; e < NEXP; e++) { p[e] = expf(lg[e] - m); se += p[e]; }
        float inv = 1.f / se;
#pragma unroll
        for (int e = 0; e < NEXP; e++) p[e] *= inv;

        int i0 = 0;
#pragma unroll
        for (int e = 1; e < NEXP; e++) if (p[e] > p[i0]) i0 = e;
        int i1 = (i0 == 0) ? 1 : 0;
#pragma unroll
        for (int e = 0; e < NEXP; e++) if (e != i0 && p[e] > p[i1]) i1 = e;

        float b = expf(p[i1] - p[i0]);
        float w0 = 1.f / (1.f + b);
        float w1s = b / (1.f + b);

        g_topki[2 * t]     = i0;  g_topki[2 * t + 1] = i1;
        g_topkw[2 * t]     = w0;  g_topkw[2 * t + 1] = w1s;
    }

    // fused weight conversion: W1 and W2 are each 8388608 float4 over 8192*256 threads
    size_t base = (size_t)t * 256 + tid;
#pragma unroll
    for (int rep = 0; rep < 4; rep++) {
        size_t i = base + (size_t)rep * 2097152;
        float4 a = reinterpret_cast<const float4*>(w1)[i];
        cvt4_store(&g_w1_16[i * 4], a);
        float4 c = reinterpret_cast<const float4*>(w2)[i];
        cvt4_store(&g_w2_16[i * 4], c);
    }
}

// ---------------- kernel 2: route = count + prefix + scatter (one block) ----------------
__global__ void route_kernel() {
    __shared__ int sc[NEXP];
    __shared__ int so[NEXP];
    int tid = threadIdx.x;                 // 1024 threads
    if (tid < NEXP) sc[tid] = 0;
    __syncthreads();
    for (int i = tid; i < NPAIR; i += 1024) atomicAdd(&sc[g_topki[i]], 1);
    __syncthreads();
    if (tid == 0) {
        int s = 0;
#pragma unroll
        for (int e = 0; e < NEXP; e++) {
            so[e] = s;
            g_off[e] = s;
            g_cnt[e] = sc[e];
            s += sc[e];
        }
        g_off[NEXP] = s;
    }
    __syncthreads();
    if (tid < NEXP) sc[tid] = so[tid];
    __syncthreads();
    for (int i = tid; i < NPAIR; i += 1024) {
        int e = g_topki[i];
        int pos = atomicAdd(&sc[e], 1);
        g_pairs[pos] = i;
        g_pairof[i] = pos;
    }
}

// ---------------- grouped GEMM: fp16, 128x128x64, 2 CTAs/SM, 2-stage (R10 proven) ----
// PASS1: g_h16 = relu(X[tok(row)] @ W1^T + b1)  K=1024, Nn=4096, A via g_pairs indirection
// PASS2: g_y   = H @ W2^T + b2                  K=4096, Nn=1024, A direct (pair order)
#define BM 128
#define BN 128
#define BK 64
#define STR 72                      // 144B rows: 16B-aligned, conflict-free LDSM phases
#define PL (BM * STR)               // per-plane elems = 9216
#define BUF_ELEMS (2 * PL)          // A|B = 18432 elems = 36864 B
#define SMEM_BYTES (2 * BUF_ELEMS * 2)   // 2 stages = 73728 B (-> 2 CTAs/SM)

template <bool PASS1>
__global__ __launch_bounds__(256, 2)
void moe_gemm(const float* __restrict__ Bias) {
    constexpr int K  = PASS1 ? DIM : HID;
    constexpr int Nn = PASS1 ? HID : DIM;
    constexpr int KT = K / BK;
    const __half* __restrict__ Wg = PASS1 ? g_w1_16 : g_w2_16;

    int e = blockIdx.z;
    int cnt = g_cnt[e];
    int m0 = blockIdx.x * BM;
    if (m0 >= cnt) return;
    int r0 = g_off[e] + m0;
    int n0 = blockIdx.y * BN;

    const __half* We = Wg + (size_t)e * Nn * K;
    const float* be = Bias + (size_t)e * Nn;

    extern __shared__ __align__(16) unsigned char smem_raw[];
    __half* smem = reinterpret_cast<__half*>(smem_raw);

    int tid = threadIdx.x;
    int wid = tid >> 5, lane = tid & 31;
    int wm = wid & 3;        // 4 warps along M: 32 rows each
    int wn = wid >> 2;       // 2 warps along N: 64 cols each

    // per-thread loader bases (8 chunks: 4 A rows + 4 B rows), resolved once.
    // PASS1: A row -> token row of g_x16 via g_pairs (clamped); PASS2: direct pair row.
    const __half* lsrc[8];
    uint32_t      ldst[8];
#pragma unroll
    for (int t = 0; t < 8; t++) {
        int id = tid + t * 256;
        int plane = id >> 10, rem = id & 1023;
        int row = rem >> 3, ch = rem & 7;
        if (plane == 0) {
            if (PASS1) {
                int pr = r0 + row; if (pr > NPAIR - 1) pr = NPAIR - 1;
                int tok = g_pairs[pr] >> 1;
                lsrc[t] = g_x16 + (size_t)tok * DIM + ch * 8;
            } else {
                lsrc[t] = g_h16 + (size_t)(r0 + row) * HID + ch * 8;
            }
            ldst[t] = row * STR + ch * 8;
        } else {
            lsrc[t] = We + (size_t)(n0 + row) * K + ch * 8;
            ldst[t] = PL + row * STR + ch * 8;
        }
    }
    auto load_panel = [&](int kt, int b) {
        const int k0 = kt * BK;
        __half* bb = smem + b * BUF_ELEMS;
#pragma unroll
        for (int t = 0; t < 8; t++) cpa16(bb + ldst[t], lsrc[t] + k0);
    };

    wmma::fragment<wmma::accumulator, 16, 16, 16, float> acc[2][4];
#pragma unroll
    for (int i = 0; i < 2; i++)
#pragma unroll
        for (int j = 0; j < 4; j++) wmma::fill_fragment(acc[i][j], 0.f);

    load_panel(0, 0);
    cp_commit();

    for (int kt = 0; kt < KT; kt++) {
        if (kt + 1 < KT) {
            load_panel(kt + 1, (kt + 1) & 1);
            cp_commit();
            cp_wait<1>();
        } else {
            cp_wait<0>();
        }
        __syncthreads();

        const __half* bA = smem + (kt & 1) * BUF_ELEMS;
        const __half* bB = bA + PL;

#pragma unroll
        for (int kk = 0; kk < 4; kk++) {
            wmma::fragment<wmma::matrix_a, 16, 16, 16, __half, wmma::row_major> a[2];
#pragma unroll
            for (int i = 0; i < 2; i++)
                wmma::load_matrix_sync(a[i], bA + (wm * 32 + i * 16) * STR + kk * 16, STR);
#pragma unroll
            for (int j = 0; j < 4; j++) {
                wmma::fragment<wmma::matrix_b, 16, 16, 16, __half, wmma::col_major> bf;
                wmma::load_matrix_sync(bf, bB + (wn * 64 + j * 16) * STR + kk * 16, STR);
#pragma unroll
                for (int i = 0; i < 2; i++)
                    wmma::mma_sync(acc[i][j], a[i], bf, acc[i][j]);
            }
        }
        __syncthreads();
    }

    // epilogue: per-warp 32x64 fp32 stage in smem (8KB/warp)
    float* stage = reinterpret_cast<float*>(smem_raw) + (size_t)wid * 2048;
#pragma unroll
    for (int i = 0; i < 2; i++)
#pragma unroll
        for (int j = 0; j < 4; j++)
            wmma::store_matrix_sync(stage + i * 16 * 64 + j * 16, acc[i][j], 64,
                                    wmma::mem_row_major);
    __syncwarp();

    int rem = cnt - m0;   // valid rows in this tile
    for (int it = lane; it < 512; it += 32) {     // 32x64 elems as float4
        int row_loc = it >> 4;
        int c4 = (it & 15) * 4;
        int rtile = wm * 32 + row_loc;
        if (rtile < rem) {
            float4 v = *reinterpret_cast<float4*>(stage + row_loc * 64 + c4);
            int gcol = n0 + wn * 64 + c4;
            float4 bv = *reinterpret_cast<const float4*>(&be[gcol]);
            v.x += bv.x; v.y += bv.y; v.z += bv.z; v.w += bv.w;
            size_t grow = (size_t)(r0 + rtile);
            if (PASS1) {
                v.x = fmaxf(v.x, 0.f); v.y = fmaxf(v.y, 0.f);
                v.z = fmaxf(v.z, 0.f); v.w = fmaxf(v.w, 0.f);
                cvt4_store(&g_h16[grow * HID + gcol], v);
            } else {
                *reinterpret_cast<float4*>(&g_y[grow * DIM + gcol]) = v;
            }
        }
    }
}

// ---------------- kernel 5: combine + residual + LayerNorm ----------------
__global__ void finalize_kernel(const float* __restrict__ x,
                                const float* __restrict__ lnw,
                                const float* __restrict__ lnb,
                                float* __restrict__ out) {
    int t = blockIdx.x;
    int tid = threadIdx.x;
    int wid = tid >> 5, lane = tid & 31;

    float w0 = g_topkw[2 * t], w1 = g_topkw[2 * t + 1];
    size_t p0 = (size_t)g_pairof[2 * t] * DIM;
    size_t p1 = (size_t)g_pairof[2 * t + 1] * DIM;

    __shared__ float r[DIM];
    __shared__ float ps[8][2];

    float s = 0.f, s2 = 0.f;
    for (int i = tid; i < DIM; i += 256) {
        float v = x[(size_t)t * DIM + i] + w0 * g_y[p0 + i] + w1 * g_y[p1 + i];
        r[i] = v;
        s += v;
        s2 += v * v;
    }
#pragma unroll
    for (int o = 16; o > 0; o >>= 1) {
        s  += __shfl_down_sync(0xffffffffu, s, o);
        s2 += __shfl_down_sync(0xffffffffu, s2, o);
    }
    if (lane == 0) { ps[wid][0] = s; ps[wid][1] = s2; }
    __syncthreads();
    if (tid == 0) {
        float a = 0.f, b = 0.f;
#pragma unroll
        for (int w = 0; w < 8; w++) { a += ps[w][0]; b += ps[w][1]; }
        float mu = a / (float)DIM;
        float var = b / (float)DIM - mu * mu;
        ps[0][0] = mu;
        ps[0][1] = rsqrtf(var + LN_EPS);
    }
    __syncthreads();
    float mu = ps[0][0], inv = ps[0][1];
    for (int i = tid; i < DIM; i += 256)
        out[(size_t)t * DIM + i] = (r[i] - mu) * inv * lnw[i] + lnb[i];
}

// ---------------- launch ----------------
extern "C" void kernel_launch(void* const* d_in, const int* in_sizes, int n_in,
                              void* d_out, int out_size) {
    (void)in_sizes; (void)n_in; (void)out_size;
    const float* x   = (const float*)d_in[0];
    const float* gw  = (const float*)d_in[1];
    const float* gb  = (const float*)d_in[2];
    const float* w1  = (const float*)d_in[3];
    const float* b1  = (const float*)d_in[4];
    const float* w2  = (const float*)d_in[5];
    const float* b2  = (const float*)d_in[6];
    const float* lnw = (const float*)d_in[7];
    const float* lnb = (const float*)d_in[8];
    float* out = (float*)d_out;

    cudaFuncSetAttribute(moe_gemm<true>,  cudaFuncAttributeMaxDynamicSharedMemorySize, SMEM_BYTES);
    cudaFuncSetAttribute(moe_gemm<false>, cudaFuncAttributeMaxDynamicSharedMemorySize, SMEM_BYTES);

    gate_kernel<<<NTOK, 256>>>(x, gw, gb, w1, w2);                     // launch 0 (+x/W1/W2 cvt)
    route_kernel<<<1, 1024>>>();                                       // launch 1
    moe_gemm<true><<<dim3(NPAIR / BM, HID / BN, NEXP), 256, SMEM_BYTES>>>(b1);   // launch 2
    moe_gemm<false><<<dim3(NPAIR / BM, DIM / BN, NEXP), 256, SMEM_BYTES>>>(b2);  // launch 3 <- ncu
    finalize_kernel<<<NTOK, 256>>>(x, lnw, lnb, out);                  // launch 4
}

// round 16
// speedup vs baseline: 1.1800x; 1.0153x over previous
#include <cuda_runtime.h>
#include <cuda_bf16.h>
#include <cuda_fp16.h>
#include <mma.h>
#include <math.h>
#include <cstdint>

using namespace nvcuda;

#define NTOK 8192
#define DIM  1024
#define HID  4096
#define NEXP 8
#define NPAIR (NTOK*2)
#define ROWPAD 128
#define LN_EPS 1e-5f

// ---------------- scratch (device globals) ----------------
__device__ float g_topkw[NPAIR];
__device__ int   g_topki[NPAIR];
__device__ int   g_cnt[NEXP];
__device__ int   g_off[NEXP + 1];
__device__ int   g_pairs[NPAIR];
__device__ int   g_pairof[NPAIR];

__device__ __half g_x16[(size_t)NTOK * DIM];                  // token order (no gather)
__device__ __half g_h16[(size_t)(NPAIR + ROWPAD) * HID];      // pair order
__device__ __half g_w1_16[(size_t)NEXP * HID * DIM];
__device__ __half g_w2_16[(size_t)NEXP * DIM * HID];
__device__ float  g_y[(size_t)NPAIR * DIM];

// ---------------- helpers ----------------
__device__ __forceinline__ void cvt4_store(__half* dst, float4 f) {
    __half2 a = __floats2half2_rn(f.x, f.y);
    __half2 b = __floats2half2_rn(f.z, f.w);
    *reinterpret_cast<__half2*>(dst)     = a;
    *reinterpret_cast<__half2*>(dst + 2) = b;
}

__device__ __forceinline__ void cpa16(void* sdst, const void* gsrc) {
    uint32_t s = (uint32_t)__cvta_generic_to_shared(sdst);
    asm volatile("cp.async.cg.shared.global [%0], [%1], 16;\n" :: "r"(s), "l"(gsrc));
}
__device__ __forceinline__ void cp_commit() { asm volatile("cp.async.commit_group;\n"); }
template <int N> __device__ __forceinline__ void cp_wait() {
    asm volatile("cp.async.wait_group %0;\n" :: "n"(N));
}

// ---------------- kernel 1: gating + x->fp16 + W1/W2 -> fp16 ----------------
__global__ void gate_kernel(const float* __restrict__ x,
                            const float* __restrict__ gw,
                            const float* __restrict__ gb,
                            const float* __restrict__ w1,
                            const float* __restrict__ w2) {
    int t = blockIdx.x;
    int tid = threadIdx.x;                 // 256 threads; 256*4 = 1024 = DIM exactly
    int wid = tid >> 5, lane = tid & 31;

    // one float4 of x per thread: feeds both the gating GEMV and the fp16 conversion
    float4 f = reinterpret_cast<const float4*>(x + (size_t)t * DIM)[tid];
    cvt4_store(&g_x16[(size_t)t * DIM + tid * 4], f);

    float acc[NEXP];
#pragma unroll
    for (int e = 0; e < NEXP; e++) {
        float4 g = reinterpret_cast<const float4*>(gw + (size_t)e * DIM)[tid];
        acc[e] = f.x * g.x + f.y * g.y + f.z * g.z + f.w * g.w;
    }
#pragma unroll
    for (int e = 0; e < NEXP; e++)
#pragma unroll
        for (int o = 16; o > 0; o >>= 1) acc[e] += __shfl_down_sync(0xffffffffu, acc[e], o);

    __shared__ float part[8][NEXP];
    if (lane == 0) {
#pragma unroll
        for (int e = 0; e < NEXP; e++) part[wid][e] = acc[e];
    }
    __syncthreads();

    if (tid == 0) {
        float lg[NEXP], p[NEXP];
#pragma unroll
        for (int e = 0; e < NEXP; e++) {
            float s = gb[e];
#pragma unroll
            for (int w = 0; w < 8; w++) s += part[w][e];
            lg[e] = s;
        }
        float m = lg[0];
#pragma unroll
        for (int e = 1; e < NEXP; e++) m = fmaxf(m, lg[e]);
        float se = 0.f;
#pragma unroll
        for (int e = 0; e < NEXP; e++) { p[e] = expf(lg[e] - m); se += p[e]; }
        float inv = 1.f / se;
#pragma unroll
        for (int e = 0; e < NEXP; e++) p[e] *= inv;

        int i0 = 0;
#pragma unroll
        for (int e = 1; e < NEXP; e++) if (p[e] > p[i0]) i0 = e;
        int i1 = (i0 == 0) ? 1 : 0;
#pragma unroll
        for (int e = 0; e < NEXP; e++) if (e != i0 && p[e] > p[i1]) i1 = e;

        float b = expf(p[i1] - p[i0]);
        float w0 = 1.f / (1.f + b);
        float w1s = b / (1.f + b);

        g_topki[2 * t]     = i0;  g_topki[2 * t + 1] = i1;
        g_topkw[2 * t]     = w0;  g_topkw[2 * t + 1] = w1s;
    }

    // fused weight conversion: W1 and W2 are each 8388608 float4 over 8192*256 threads
    size_t base = (size_t)t * 256 + tid;
#pragma unroll
    for (int rep = 0; rep < 4; rep++) {
        size_t i = base + (size_t)rep * 2097152;
        float4 a = reinterpret_cast<const float4*>(w1)[i];
        cvt4_store(&g_w1_16[i * 4], a);
        float4 c = reinterpret_cast<const float4*>(w2)[i];
        cvt4_store(&g_w2_16[i * 4], c);
    }
}

// ---------------- kernel 2: route — two-level (per-warp counters kill contention) ----
__global__ void route_kernel() {
    __shared__ int sc[32][NEXP];   // per-warp counts, then reused as per-warp cursors
    int tid = threadIdx.x;         // 1024 threads = 32 warps; 512 items per warp
    int wid = tid >> 5, lane = tid & 31;

    if (tid < 32 * NEXP) reinterpret_cast<int*>(sc)[tid] = 0;
    __syncthreads();

    int i0 = wid * 512 + lane;
    // pass 1: per-warp histogram (contention: ~64 ops/address within one warp)
    for (int i = i0; i < wid * 512 + 512; i += 32) atomicAdd(&sc[wid][g_topki[i]], 1);
    __syncthreads();

    // serial prefix over 256 cells: global expert offsets + per-warp bases
    if (tid == 0) {
        int s = 0;
#pragma unroll
        for (int e = 0; e < NEXP; e++) {
            g_off[e] = s;
            int t = s;
            for (int w = 0; w < 32; w++) { int c = sc[w][e]; sc[w][e] = t; t += c; }
            g_cnt[e] = t - s;
            s = t;
        }
        g_off[NEXP] = s;
    }
    __syncthreads();

    // pass 2: scatter through per-warp cursors (same low contention)
    for (int i = i0; i < wid * 512 + 512; i += 32) {
        int e = g_topki[i];
        int pos = atomicAdd(&sc[wid][e], 1);
        g_pairs[pos] = i;
        g_pairof[i] = pos;
    }
}

// ---------------- grouped GEMM: fp16, 128x128x64, 2 CTAs/SM, 2-stage (R10 proven) ----
// PASS1: g_h16 = relu(X[tok(row)] @ W1^T + b1)  K=1024, Nn=4096, A via g_pairs indirection
// PASS2: g_y   = H @ W2^T + b2                  K=4096, Nn=1024, A direct (pair order)
#define BM 128
#define BN 128
#define BK 64
#define STR 72                      // 144B rows: 16B-aligned, conflict-free LDSM phases
#define PL (BM * STR)               // per-plane elems = 9216
#define BUF_ELEMS (2 * PL)          // A|B = 18432 elems = 36864 B
#define SMEM_BYTES (2 * BUF_ELEMS * 2)   // 2 stages = 73728 B (-> 2 CTAs/SM)

template <bool PASS1>
__global__ __launch_bounds__(256, 2)
void moe_gemm(const float* __restrict__ Bias) {
    constexpr int K  = PASS1 ? DIM : HID;
    constexpr int Nn = PASS1 ? HID : DIM;
    constexpr int KT = K / BK;
    const __half* __restrict__ Wg = PASS1 ? g_w1_16 : g_w2_16;

    int e = blockIdx.z;
    int cnt = g_cnt[e];
    int m0 = blockIdx.x * BM;
    if (m0 >= cnt) return;
    int r0 = g_off[e] + m0;
    int n0 = blockIdx.y * BN;

    const __half* We = Wg + (size_t)e * Nn * K;
    const float* be = Bias + (size_t)e * Nn;

    extern __shared__ __align__(16) unsigned char smem_raw[];
    __half* smem = reinterpret_cast<__half*>(smem_raw);

    int tid = threadIdx.x;
    int wid = tid >> 5, lane = tid & 31;
    int wm = wid & 3;        // 4 warps along M: 32 rows each
    int wn = wid >> 2;       // 2 warps along N: 64 cols each

    // per-thread loader bases (8 chunks: 4 A rows + 4 B rows), resolved once.
    // PASS1: A row -> token row of g_x16 via g_pairs (clamped); PASS2: direct pair row.
    const __half* lsrc[8];
    uint32_t      ldst[8];
#pragma unroll
    for (int t = 0; t < 8; t++) {
        int id = tid + t * 256;
        int plane = id >> 10, rem = id & 1023;
        int row = rem >> 3, ch = rem & 7;
        if (plane == 0) {
            if (PASS1) {
                int pr = r0 + row; if (pr > NPAIR - 1) pr = NPAIR - 1;
                int tok = g_pairs[pr] >> 1;
                lsrc[t] = g_x16 + (size_t)tok * DIM + ch * 8;
            } else {
                lsrc[t] = g_h16 + (size_t)(r0 + row) * HID + ch * 8;
            }
            ldst[t] = row * STR + ch * 8;
        } else {
            lsrc[t] = We + (size_t)(n0 + row) * K + ch * 8;
            ldst[t] = PL + row * STR + ch * 8;
        }
    }
    auto load_panel = [&](int kt, int b) {
        const int k0 = kt * BK;
        __half* bb = smem + b * BUF_ELEMS;
#pragma unroll
        for (int t = 0; t < 8; t++) cpa16(bb + ldst[t], lsrc[t] + k0);
    };

    wmma::fragment<wmma::accumulator, 16, 16, 16, float> acc[2][4];
#pragma unroll
    for (int i = 0; i < 2; i++)
#pragma unroll
        for (int j = 0; j < 4; j++) wmma::fill_fragment(acc[i][j], 0.f);

    load_panel(0, 0);
    cp_commit();

    for (int kt = 0; kt < KT; kt++) {
        if (kt + 1 < KT) {
            load_panel(kt + 1, (kt + 1) & 1);
            cp_commit();
            cp_wait<1>();
        } else {
            cp_wait<0>();
        }
        __syncthreads();

        const __half* bA = smem + (kt & 1) * BUF_ELEMS;
        const __half* bB = bA + PL;

#pragma unroll
        for (int kk = 0; kk < 4; kk++) {
            wmma::fragment<wmma::matrix_a, 16, 16, 16, __half, wmma::row_major> a[2];
#pragma unroll
            for (int i = 0; i < 2; i++)
                wmma::load_matrix_sync(a[i], bA + (wm * 32 + i * 16) * STR + kk * 16, STR);
#pragma unroll
            for (int j = 0; j < 4; j++) {
                wmma::fragment<wmma::matrix_b, 16, 16, 16, __half, wmma::col_major> bf;
                wmma::load_matrix_sync(bf, bB + (wn * 64 + j * 16) * STR + kk * 16, STR);
#pragma unroll
                for (int i = 0; i < 2; i++)
                    wmma::mma_sync(acc[i][j], a[i], bf, acc[i][j]);
            }
        }
        __syncthreads();
    }

    // epilogue: per-warp 32x64 fp32 stage in smem (8KB/warp)
    float* stage = reinterpret_cast<float*>(smem_raw) + (size_t)wid * 2048;
#pragma unroll
    for (int i = 0; i < 2; i++)
#pragma unroll
        for (int j = 0; j < 4; j++)
            wmma::store_matrix_sync(stage + i * 16 * 64 + j * 16, acc[i][j], 64,
                                    wmma::mem_row_major);
    __syncwarp();

    int rem = cnt - m0;   // valid rows in this tile
    for (int it = lane; it < 512; it += 32) {     // 32x64 elems as float4
        int row_loc = it >> 4;
        int c4 = (it & 15) * 4;
        int rtile = wm * 32 + row_loc;
        if (rtile < rem) {
            float4 v = *reinterpret_cast<float4*>(stage + row_loc * 64 + c4);
            int gcol = n0 + wn * 64 + c4;
            float4 bv = *reinterpret_cast<const float4*>(&be[gcol]);
            v.x += bv.x; v.y += bv.y; v.z += bv.z; v.w += bv.w;
            size_t grow = (size_t)(r0 + rtile);
            if (PASS1) {
                v.x = fmaxf(v.x, 0.f); v.y = fmaxf(v.y, 0.f);
                v.z = fmaxf(v.z, 0.f); v.w = fmaxf(v.w, 0.f);
                cvt4_store(&g_h16[grow * HID + gcol], v);
            } else {
                *reinterpret_cast<float4*>(&g_y[grow * DIM + gcol]) = v;
            }
        }
    }
}

// ---------------- kernel 5: combine + residual + LayerNorm (float4, register-resident) --
__global__ void finalize_kernel(const float* __restrict__ x,
                                const float* __restrict__ lnw,
                                const float* __restrict__ lnb,
                                float* __restrict__ out) {
    int t = blockIdx.x;
    int tid = threadIdx.x;                 // 256 threads, 1 float4 each (DIM=1024)
    int wid = tid >> 5, lane = tid & 31;

    float w0 = g_topkw[2 * t], w1 = g_topkw[2 * t + 1];
    size_t p0 = (size_t)g_pairof[2 * t] * DIM;
    size_t p1 = (size_t)g_pairof[2 * t + 1] * DIM;

    float4 xv = reinterpret_cast<const float4*>(x + (size_t)t * DIM)[tid];
    float4 y0 = reinterpret_cast<const float4*>(g_y + p0)[tid];
    float4 y1 = reinterpret_cast<const float4*>(g_y + p1)[tid];

    float4 v;
    v.x = xv.x + w0 * y0.x + w1 * y1.x;
    v.y = xv.y + w0 * y0.y + w1 * y1.y;
    v.z = xv.z + w0 * y0.z + w1 * y1.z;
    v.w = xv.w + w0 * y0.w + w1 * y1.w;

    float s  = v.x + v.y + v.z + v.w;
    float s2 = v.x * v.x + v.y * v.y + v.z * v.z + v.w * v.w;
#pragma unroll
    for (int o = 16; o > 0; o >>= 1) {
        s  += __shfl_down_sync(0xffffffffu, s, o);
        s2 += __shfl_down_sync(0xffffffffu, s2, o);
    }
    __shared__ float ps[8][2];
    if (lane == 0) { ps[wid][0] = s; ps[wid][1] = s2; }
    __syncthreads();
    if (tid == 0) {
        float a = 0.f, b = 0.f;
#pragma unroll
        for (int w = 0; w < 8; w++) { a += ps[w][0]; b += ps[w][1]; }
        float mu = a / (float)DIM;
        float var = b / (float)DIM - mu * mu;
        ps[0][0] = mu;
        ps[0][1] = rsqrtf(var + LN_EPS);
    }
    __syncthreads();
    float mu = ps[0][0], inv = ps[0][1];

    float4 lw = reinterpret_cast<const float4*>(lnw)[tid];
    float4 lb = reinterpret_cast<const float4*>(lnb)[tid];
    float4 o;
    o.x = (v.x - mu) * inv * lw.x + lb.x;
    o.y = (v.y - mu) * inv * lw.y + lb.y;
    o.z = (v.z - mu) * inv * lw.z + lb.z;
    o.w = (v.w - mu) * inv * lw.w + lb.w;
    reinterpret_cast<float4*>(out + (size_t)t * DIM)[tid] = o;
}

// ---------------- launch ----------------
extern "C" void kernel_launch(void* const* d_in, const int* in_sizes, int n_in,
                              void* d_out, int out_size) {
    (void)in_sizes; (void)n_in; (void)out_size;
    const float* x   = (const float*)d_in[0];
    const float* gw  = (const float*)d_in[1];
    const float* gb  = (const float*)d_in[2];
    const float* w1  = (const float*)d_in[3];
    const float* b1  = (const float*)d_in[4];
    const float* w2  = (const float*)d_in[5];
    const float* b2  = (const float*)d_in[6];
    const float* lnw = (const float*)d_in[7];
    const float* lnb = (const float*)d_in[8];
    float* out = (float*)d_out;

    cudaFuncSetAttribute(moe_gemm<true>,  cudaFuncAttributeMaxDynamicSharedMemorySize, SMEM_BYTES);
    cudaFuncSetAttribute(moe_gemm<false>, cudaFuncAttributeMaxDynamicSharedMemorySize, SMEM_BYTES);

    gate_kernel<<<NTOK, 256>>>(x, gw, gb, w1, w2);                     // launch 0 (+x/W1/W2 cvt)
    route_kernel<<<1, 1024>>>();                                       // launch 1
    moe_gemm<true><<<dim3(NPAIR / BM, HID / BN, NEXP), 256, SMEM_BYTES>>>(b1);   // launch 2
    moe_gemm<false><<<dim3(NPAIR / BM, DIM / BN, NEXP), 256, SMEM_BYTES>>>(b2);  // launch 3 <- ncu
    finalize_kernel<<<NTOK, 256>>>(x, lnw, lnb, out);                  // launch 4
}